// round 1
// baseline (speedup 1.0000x reference)
#include <cuda_runtime.h>
#include <math.h>

// ---------------- problem constants ----------------
#define B_    2
#define S_    1024
#define HID_  4096
#define H_    32
#define D_    128
#define KVH_  8
#define EHID_ 1024
#define EH_   8
#define AH_   256
#define NTOK  (B_*S_)          // 2048
#define NHV   (NTOK*EH_)       // 16384 per-head vectors for adapters

// ---------------- scratch (static device memory; no allocation) ----------------
__device__ float g_qt [NTOK*HID_];    // text Q       [B,S,32,128]
__device__ float g_kt [NTOK*EHID_];   // text K base  [B,S,8,128]
__device__ float g_vt [NTOK*EHID_];   // text V base  [B,S,8,128]
__device__ float g_pre[NTOK*EHID_];   // entity pre-adapter / mean buffer
__device__ float g_tmp[NHV*AH_];      // adapter hidden [16384,256]
__device__ float g_qe [NTOK*EHID_];   // entity Q base [B,S,8,128]
__device__ float g_ke [NTOK*EHID_];
__device__ float g_ve [NTOK*EHID_];
__device__ float g_q  [NTOK*HID_];    // roped Q [B,H,S,D]
__device__ float g_k  [NTOK*EHID_];   // roped K [B,8,S,D]
__device__ float g_v  [NTOK*EHID_];   // V       [B,8,S,D]
__device__ float g_att[NTOK*HID_];    // attention out [B,S,H,D]
__device__ float g_oe [NTOK*EHID_];   // ao-adapter out

// ---------------- helpers ----------------
__device__ __forceinline__ float gelu_exact(float x) {
    return 0.5f * x * (1.0f + erff(x * 0.70710678118654752f));
}

// ---------------- generic SGEMM: C[M,N] = A[M,K] @ B[K,N] (+bias)(+gelu) ----------------
// BM=BN=64, BK=16, 256 threads, 4x4 microtile. All dims divide tiles exactly.
__global__ void __launch_bounds__(256)
sgemm_k(const float* __restrict__ A, const float* __restrict__ B,
        const float* __restrict__ bias, float* __restrict__ C,
        int M, int N, int K, int epi)   // epi: 0 none, 1 +bias, 2 +bias+gelu
{
    __shared__ float As[16][64];
    __shared__ float Bs[16][64];
    const int tid = threadIdx.x;
    const int tx = tid & 15;       // 0..15 -> 4 output cols each
    const int ty = tid >> 4;       // 0..15 -> 4 output rows each
    const int rowBase = blockIdx.y * 64;
    const int colBase = blockIdx.x * 64;

    float acc[4][4];
#pragma unroll
    for (int i = 0; i < 4; i++)
#pragma unroll
        for (int j = 0; j < 4; j++) acc[i][j] = 0.f;

    for (int k0 = 0; k0 < K; k0 += 16) {
#pragma unroll
        for (int i = 0; i < 4; i++) {
            int idx = tid + i * 256;          // 0..1023
            int r = idx >> 4, c = idx & 15;   // A tile 64x16
            As[c][r] = A[(size_t)(rowBase + r) * K + k0 + c];
        }
#pragma unroll
        for (int i = 0; i < 4; i++) {
            int idx = tid + i * 256;
            int r = idx >> 6, c = idx & 63;   // B tile 16x64
            Bs[r][c] = B[(size_t)(k0 + r) * N + colBase + c];
        }
        __syncthreads();
#pragma unroll
        for (int k = 0; k < 16; k++) {
            float a[4], b[4];
#pragma unroll
            for (int i = 0; i < 4; i++) a[i] = As[k][ty * 4 + i];
#pragma unroll
            for (int j = 0; j < 4; j++) b[j] = Bs[k][tx * 4 + j];
#pragma unroll
            for (int i = 0; i < 4; i++)
#pragma unroll
                for (int j = 0; j < 4; j++)
                    acc[i][j] = fmaf(a[i], b[j], acc[i][j]);
        }
        __syncthreads();
    }

#pragma unroll
    for (int i = 0; i < 4; i++) {
        int r = rowBase + ty * 4 + i;
#pragma unroll
        for (int j = 0; j < 4; j++) {
            int c = colBase + tx * 4 + j;
            float v = acc[i][j];
            if (epi >= 1) v += bias[c];
            if (epi == 2) v = gelu_exact(v);
            C[(size_t)r * N + c] = v;
        }
    }
}

// ---------------- token-type select + RoPE for Q (32 heads) ----------------
// out layout: g_q[B,H,S,D]
__global__ void __launch_bounds__(256)
select_rope_q(const int* __restrict__ ttm, const int* __restrict__ pos_ids)
{
    int idx = blockIdx.x * 256 + threadIdx.x;      // B*S*H*64
    int d  = idx & 63;
    int h  = (idx >> 6) & 31;
    int s  = (idx >> 11) & 1023;
    int b  = idx >> 21;
    int bs = b * S_ + s;

    bool is_e = (ttm[bs] == 1);
    const float* src = is_e ? &g_qe[((size_t)bs * 8 + (h & 7)) * 128]
                            : &g_qt[((size_t)bs * 32 + h) * 128];
    float x1 = src[d], x2 = src[d + 64];

    float inv = powf(10000.0f, -(float)d * (1.0f / 64.0f));
    float th  = (float)pos_ids[bs] * inv;
    float cs, sn; sincosf(th, &sn, &cs);

    float* dst = &g_q[(((size_t)b * 32 + h) * 1024 + s) * 128];
    dst[d]      = x1 * cs - x2 * sn;
    dst[d + 64] = x2 * cs + x1 * sn;
}

// ---------------- token-type select + RoPE for K, plain select for V (8 heads) ----------------
__global__ void __launch_bounds__(256)
select_rope_kv(const int* __restrict__ ttm, const int* __restrict__ pos_ids)
{
    int idx = blockIdx.x * 256 + threadIdx.x;      // B*S*8*64
    int d  = idx & 63;
    int h  = (idx >> 6) & 7;
    int s  = (idx >> 9) & 1023;
    int b  = idx >> 19;
    int bs = b * S_ + s;

    bool is_e = (ttm[bs] == 1);
    size_t srcOff = ((size_t)bs * 8 + h) * 128;
    const float* ks = is_e ? &g_ke[srcOff] : &g_kt[srcOff];
    const float* vs = is_e ? &g_ve[srcOff] : &g_vt[srcOff];

    float inv = powf(10000.0f, -(float)d * (1.0f / 64.0f));
    float th  = (float)pos_ids[bs] * inv;
    float cs, sn; sincosf(th, &sn, &cs);

    size_t dstOff = (((size_t)b * 8 + h) * 1024 + s) * 128;
    float k1 = ks[d], k2 = ks[d + 64];
    g_k[dstOff + d]      = k1 * cs - k2 * sn;
    g_k[dstOff + d + 64] = k2 * cs + k1 * sn;
    g_v[dstOff + d]      = vs[d];
    g_v[dstOff + d + 64] = vs[d + 64];
}

// ---------------- causal flash attention (GQA 32q -> 8kv), fp32 ----------------
// grid: (S/64, H, B), 256 threads. smem: Q,K,V tiles 64x128 each (96KB dynamic).
__global__ void __launch_bounds__(256)
flash_kernel()
{
    extern __shared__ float sm[];
    float* Qs = sm;
    float* Ks = sm + 64 * 128;
    float* Vs = sm + 2 * 64 * 128;

    const int qt  = blockIdx.x;
    const int h   = blockIdx.y;
    const int b   = blockIdx.z;
    const int tid = threadIdx.x;
    const int r   = tid >> 2;     // 0..63 q-row within tile
    const int seg = tid & 3;      // 32-wide d slice

    const float SCALE = 0.08838834764831845f;  // 1/sqrt(128)

    const float* Qg = g_q + (((size_t)b * 32 + h) * 1024 + qt * 64) * 128;
    const float* Kg = g_k + ((size_t)b * 8 + (h & 7)) * 1024 * 128;
    const float* Vg = g_v + ((size_t)b * 8 + (h & 7)) * 1024 * 128;

    for (int i = tid; i < 64 * 128 / 4; i += 256)
        ((float4*)Qs)[i] = ((const float4*)Qg)[i];
    __syncthreads();

    float4 Qr[8];
#pragma unroll
    for (int i = 0; i < 8; i++)
        Qr[i] = ((const float4*)(Qs + r * 128 + seg * 32))[i];

    float m = -1e30f, l = 0.f;
    float4 Oa[8];
#pragma unroll
    for (int i = 0; i < 8; i++) Oa[i] = make_float4(0.f, 0.f, 0.f, 0.f);

    const int qrow = qt * 64 + r;

    for (int kt = 0; kt <= qt; kt++) {
        __syncthreads();
        for (int i = tid; i < 64 * 128 / 4; i += 256) {
            ((float4*)Ks)[i] = ((const float4*)(Kg + (size_t)kt * 64 * 128))[i];
            ((float4*)Vs)[i] = ((const float4*)(Vg + (size_t)kt * 64 * 128))[i];
        }
        __syncthreads();

        float p[64];
#pragma unroll 4
        for (int c = 0; c < 64; c++) {
            const float4* Kc = (const float4*)(Ks + c * 128 + seg * 32);
            float dacc = 0.f;
#pragma unroll
            for (int i = 0; i < 8; i++) {
                float4 kk = Kc[i];
                dacc += Qr[i].x * kk.x + Qr[i].y * kk.y
                      + Qr[i].z * kk.z + Qr[i].w * kk.w;
            }
            dacc += __shfl_xor_sync(0xffffffff, dacc, 1);
            dacc += __shfl_xor_sync(0xffffffff, dacc, 2);
            int kcol = kt * 64 + c;
            p[c] = (kcol <= qrow) ? dacc * SCALE : -1e30f;
        }

        float mloc = p[0];
#pragma unroll
        for (int c = 1; c < 64; c++) mloc = fmaxf(mloc, p[c]);
        float mnew = fmaxf(m, mloc);
        float corr = expf(m - mnew);
        float sum = 0.f;
#pragma unroll 4
        for (int c = 0; c < 64; c++) {
            p[c] = expf(p[c] - mnew);
            sum += p[c];
        }
        l = l * corr + sum;
        m = mnew;
#pragma unroll
        for (int i = 0; i < 8; i++) {
            Oa[i].x *= corr; Oa[i].y *= corr; Oa[i].z *= corr; Oa[i].w *= corr;
        }
#pragma unroll 4
        for (int c = 0; c < 64; c++) {
            float ec = p[c];
            const float4* Vc = (const float4*)(Vs + c * 128 + seg * 32);
#pragma unroll
            for (int i = 0; i < 8; i++) {
                float4 vv = Vc[i];
                Oa[i].x += ec * vv.x; Oa[i].y += ec * vv.y;
                Oa[i].z += ec * vv.z; Oa[i].w += ec * vv.w;
            }
        }
    }

    float invl = 1.0f / l;
    float4* Og = (float4*)(g_att + (((size_t)b * 1024 + qrow) * 32 + h) * 128 + seg * 32);
#pragma unroll
    for (int i = 0; i < 8; i++) {
        float4 o = Oa[i];
        o.x *= invl; o.y *= invl; o.z *= invl; o.w *= invl;
        Og[i] = o;
    }
}

// ---------------- mean over the 4 rep-groups: [B,S,32,128] -> [B,S,8,128] ----------------
__global__ void __launch_bounds__(256)
mean_heads()
{
    int idx = blockIdx.x * 256 + threadIdx.x;   // NTOK*1024
    int bs = idx >> 10;
    int w  = idx & 1023;
    int i  = w >> 7, d = w & 127;
    const float* base = g_att + (size_t)bs * 4096 + i * 128 + d;
    g_pre[idx] = 0.25f * (base[0] + base[8 * 128] + base[16 * 128] + base[24 * 128]);
}

// ---------------- final masking of the two output regions ----------------
__global__ void __launch_bounds__(256)
mask_outputs(float* __restrict__ out, const int* __restrict__ ttm)
{
    int idx = blockIdx.x * 256 + threadIdx.x;
    const int text_total = NTOK * HID_;
    if (idx < text_total) {
        int row = idx >> 12;                 // / 4096
        if (ttm[row] == 1) out[idx] = 0.f;
    } else {
        int j = idx - text_total;            // < NTOK*EHID_
        int row = j >> 10;                   // / 1024
        if (ttm[row] == 0) out[idx] = 0.f;
    }
}

// ---------------- host-side ----------------
static float* sym_addr(const void* sym) {
    void* p = nullptr;
    cudaGetSymbolAddress(&p, sym);
    return (float*)p;
}

extern "C" void kernel_launch(void* const* d_in, const int* in_sizes, int n_in,
                              void* d_out, int out_size)
{
    const float* x_text  = (const float*)d_in[0];
    const float* x_ent   = (const float*)d_in[1];
    const float* wq_t    = (const float*)d_in[2];
    const float* wk_t    = (const float*)d_in[3];
    const float* wv_t    = (const float*)d_in[4];
    const float* wo_t    = (const float*)d_in[5];
    const float* wq_e    = (const float*)d_in[6];
    const float* wk_e    = (const float*)d_in[7];
    const float* wv_e    = (const float*)d_in[8];
    const float* wo_e    = (const float*)d_in[9];
    const float* aq1_w   = (const float*)d_in[10];
    const float* aq1_b   = (const float*)d_in[11];
    const float* aq2_w   = (const float*)d_in[12];
    const float* aq2_b   = (const float*)d_in[13];
    const float* ak1_w   = (const float*)d_in[14];
    const float* ak1_b   = (const float*)d_in[15];
    const float* ak2_w   = (const float*)d_in[16];
    const float* ak2_b   = (const float*)d_in[17];
    const float* av1_w   = (const float*)d_in[18];
    const float* av1_b   = (const float*)d_in[19];
    const float* av2_w   = (const float*)d_in[20];
    const float* av2_b   = (const float*)d_in[21];
    const float* ao1_w   = (const float*)d_in[22];
    const float* ao1_b   = (const float*)d_in[23];
    const float* ao2_w   = (const float*)d_in[24];
    const float* ao2_b   = (const float*)d_in[25];
    // d_in[26] = attention_mask (pure causal; implemented analytically)
    const int*   ttm     = (const int*)d_in[27];
    const int*   pos_ids = (const int*)d_in[28];

    float* out = (float*)d_out;
    float* out_text = out;                         // [2048, 4096]
    float* out_ent  = out + (size_t)NTOK * HID_;   // [2048, 1024]

    float* p_qt  = sym_addr(g_qt);
    float* p_kt  = sym_addr(g_kt);
    float* p_vt  = sym_addr(g_vt);
    float* p_pre = sym_addr(g_pre);
    float* p_tmp = sym_addr(g_tmp);
    float* p_qe  = sym_addr(g_qe);
    float* p_ke  = sym_addr(g_ke);
    float* p_ve  = sym_addr(g_ve);
    float* p_att = sym_addr(g_att);
    float* p_oe  = sym_addr(g_oe);

    static bool attr_set = false;
    if (!attr_set) {
        cudaFuncSetAttribute(flash_kernel,
                             cudaFuncAttributeMaxDynamicSharedMemorySize, 98304);
        attr_set = true;
    }

    dim3 blk(256);
    auto gemm = [&](const float* A, const float* Bm, const float* bias,
                    float* C, int M, int N, int K, int epi) {
        dim3 grid(N / 64, M / 64);
        sgemm_k<<<grid, blk>>>(A, Bm, bias, C, M, N, K, epi);
    };

    // ---- text projections ----
    gemm(x_text, wq_t, nullptr, p_qt, NTOK, HID_, HID_, 0);
    gemm(x_text, wk_t, nullptr, p_kt, NTOK, EHID_, HID_, 0);
    gemm(x_text, wv_t, nullptr, p_vt, NTOK, EHID_, HID_, 0);

    // ---- entity projections + adapters ----
    gemm(x_ent, wq_e, nullptr, p_pre, NTOK, EHID_, EHID_, 0);
    gemm(p_pre, aq1_w, aq1_b, p_tmp, NHV, AH_, D_, 2);
    gemm(p_tmp, aq2_w, aq2_b, p_qe, NHV, D_, AH_, 1);

    gemm(x_ent, wk_e, nullptr, p_pre, NTOK, EHID_, EHID_, 0);
    gemm(p_pre, ak1_w, ak1_b, p_tmp, NHV, AH_, D_, 2);
    gemm(p_tmp, ak2_w, ak2_b, p_ke, NHV, D_, AH_, 1);

    gemm(x_ent, wv_e, nullptr, p_pre, NTOK, EHID_, EHID_, 0);
    gemm(p_pre, av1_w, av1_b, p_tmp, NHV, AH_, D_, 2);
    gemm(p_tmp, av2_w, av2_b, p_ve, NHV, D_, AH_, 1);

    // ---- select by token type + RoPE ----
    select_rope_q <<<(B_*S_*H_*64) / 256, blk>>>(ttm, pos_ids);
    select_rope_kv<<<(B_*S_*KVH_*64) / 256, blk>>>(ttm, pos_ids);

    // ---- causal flash attention (GQA 32->8) ----
    {
        dim3 grid(S_ / 64, H_, B_);
        flash_kernel<<<grid, blk, 98304>>>();
    }

    // ---- text output projection (into d_out) ----
    gemm(p_att, wo_t, nullptr, out_text, NTOK, HID_, HID_, 0);

    // ---- entity output path: mean -> adapter -> projection ----
    mean_heads<<<(NTOK * EHID_) / 256, blk>>>();
    gemm(p_pre, ao1_w, ao1_b, p_tmp, NHV, AH_, D_, 2);
    gemm(p_tmp, ao2_w, ao2_b, p_oe, NHV, D_, AH_, 1);
    gemm(p_oe, wo_e, nullptr, out_ent, NTOK, EHID_, EHID_, 0);

    // ---- token-type masking of both regions ----
    {
        int total = NTOK * HID_ + NTOK * EHID_;
        mask_outputs<<<(total + 255) / 256, blk>>>(out, ttm);
    }
}

// round 2
// speedup vs baseline: 1.8435x; 1.8435x over previous
#include <cuda_runtime.h>
#include <math.h>
#include <stdint.h>

// ---------------- problem constants ----------------
#define B_    2
#define S_    1024
#define HID_  4096
#define H_    32
#define D_    128
#define KVH_  8
#define EHID_ 1024
#define EH_   8
#define AH_   256
#define NTOK  (B_*S_)          // 2048
#define NHV   (NTOK*EH_)       // 16384 per-head vectors for adapters

// ---------------- scratch (static device memory; no allocation) ----------------
__device__ float g_qt [NTOK*HID_];    // text Q       [B,S,32,128]
__device__ float g_kt [NTOK*EHID_];   // text K base  [B,S,8,128]
__device__ float g_vt [NTOK*EHID_];   // text V base  [B,S,8,128]
__device__ float g_pre[NTOK*EHID_];   // entity pre-adapter / mean buffer
__device__ float g_tmp[NHV*AH_];      // adapter hidden [16384,256]
__device__ float g_qe [NTOK*EHID_];   // entity Q base [B,S,8,128]
__device__ float g_ke [NTOK*EHID_];
__device__ float g_ve [NTOK*EHID_];
__device__ float g_q  [NTOK*HID_];    // roped Q [B,H,S,D]
__device__ float g_k  [NTOK*EHID_];   // roped K [B,8,S,D]
__device__ float g_v  [NTOK*EHID_];   // V       [B,8,S,D]
__device__ float g_att[NTOK*HID_];    // attention out [B,S,H,D]
__device__ float g_oe [NTOK*EHID_];   // ao-adapter out

// ---------------- helpers ----------------
__device__ __forceinline__ float gelu_exact(float x) {
    return 0.5f * x * (1.0f + erff(x * 0.70710678118654752f));
}

__device__ __forceinline__ uint32_t f2tf32(float x) {
    uint32_t r;
    asm("cvt.rna.tf32.f32 %0, %1;" : "=r"(r) : "f"(x));
    return r;
}

__device__ __forceinline__ void mma_tf32(float c[4], const uint32_t a[4], const uint32_t b[2]) {
    asm volatile(
        "mma.sync.aligned.m16n8k8.row.col.f32.tf32.tf32.f32 "
        "{%0,%1,%2,%3}, {%4,%5,%6,%7}, {%8,%9}, {%0,%1,%2,%3};"
        : "+f"(c[0]), "+f"(c[1]), "+f"(c[2]), "+f"(c[3])
        : "r"(a[0]), "r"(a[1]), "r"(a[2]), "r"(a[3]), "r"(b[0]), "r"(b[1]));
}

// ---------------- TF32 tensor-core GEMM ----------------
// C[M,N] = A[M,K] @ B[K,N] (+bias)(+gelu)
// CTA tile 128x128, BK=32. 256 threads = 8 warps (2 along M x 4 along N),
// warp tile 64x32, per-warp 4x4 mma(16x8) tiles.
// Smem k-major with stride 136 -> conflict-free fragment LDS.
#define SA 136

__global__ void __launch_bounds__(256, 1)
gemm_tc(const float* __restrict__ A, const float* __restrict__ Bm,
        const float* __restrict__ bias, float* __restrict__ C,
        int M, int N, int K, int epi)   // epi: 0 none, 1 +bias, 2 +bias+gelu
{
    __shared__ float As[32 * SA];
    __shared__ float Bs[32 * SA];

    const int tid  = threadIdx.x;
    const int lane = tid & 31;
    const int lq   = lane >> 2;     // 0..7
    const int lr   = lane & 3;      // 0..3
    const int warp = tid >> 5;
    const int wm   = (warp & 1) * 64;
    const int wn   = (warp >> 1) * 32;
    const int rowBase = blockIdx.y * 128;
    const int colBase = blockIdx.x * 128;

    // loader indices
    const int a_m  = tid & 127;          // lane-contiguous m rows (conflict-free STS)
    const int a_kg = (tid >> 7) << 4;    // 0 or 16 (k offset within BK)
    const int b_n4 = (tid & 31) << 2;    // 0..124 step 4 (coalesced + conflict-free)
    const int b_kr = tid >> 5;           // 0..7

    const float* Aptr = A  + (size_t)(rowBase + a_m) * K + a_kg;
    const float* Bptr = Bm + (size_t)b_kr * N + colBase + b_n4;

    float4 rA[4], rB[4];
#pragma unroll
    for (int i = 0; i < 4; i++) rA[i] = *(const float4*)(Aptr + 4 * i);
#pragma unroll
    for (int i = 0; i < 4; i++) rB[i] = *(const float4*)(Bptr + (size_t)(8 * i) * N);

    float acc[4][4][4];
#pragma unroll
    for (int mt = 0; mt < 4; mt++)
#pragma unroll
        for (int nt = 0; nt < 4; nt++)
#pragma unroll
            for (int i = 0; i < 4; i++) acc[mt][nt][i] = 0.f;

    for (int k0 = 0; k0 < K; k0 += 32) {
        // store prefetched tile to smem (tf32-rounded)
#pragma unroll
        for (int i = 0; i < 4; i++) {
            As[(a_kg + 4 * i + 0) * SA + a_m] = __uint_as_float(f2tf32(rA[i].x));
            As[(a_kg + 4 * i + 1) * SA + a_m] = __uint_as_float(f2tf32(rA[i].y));
            As[(a_kg + 4 * i + 2) * SA + a_m] = __uint_as_float(f2tf32(rA[i].z));
            As[(a_kg + 4 * i + 3) * SA + a_m] = __uint_as_float(f2tf32(rA[i].w));
        }
#pragma unroll
        for (int i = 0; i < 4; i++) {
            float4 t = rB[i];
            float4 u;
            u.x = __uint_as_float(f2tf32(t.x));
            u.y = __uint_as_float(f2tf32(t.y));
            u.z = __uint_as_float(f2tf32(t.z));
            u.w = __uint_as_float(f2tf32(t.w));
            *(float4*)&Bs[(b_kr + 8 * i) * SA + b_n4] = u;
        }
        __syncthreads();

        // prefetch next tile while computing on smem
        if (k0 + 32 < K) {
#pragma unroll
            for (int i = 0; i < 4; i++)
                rA[i] = *(const float4*)(Aptr + k0 + 32 + 4 * i);
#pragma unroll
            for (int i = 0; i < 4; i++)
                rB[i] = *(const float4*)(Bptr + (size_t)(k0 + 32 + 8 * i) * N);
        }

#pragma unroll
        for (int ks = 0; ks < 4; ks++) {
            const int kb = ks * 8;
            uint32_t a[4][4], bf[4][2];
#pragma unroll
            for (int mt = 0; mt < 4; mt++) {
                int m0 = wm + mt * 16 + lq;
                a[mt][0] = __float_as_uint(As[(kb + lr) * SA + m0]);
                a[mt][1] = __float_as_uint(As[(kb + lr) * SA + m0 + 8]);
                a[mt][2] = __float_as_uint(As[(kb + lr + 4) * SA + m0]);
                a[mt][3] = __float_as_uint(As[(kb + lr + 4) * SA + m0 + 8]);
            }
#pragma unroll
            for (int nt = 0; nt < 4; nt++) {
                int n0 = wn + nt * 8 + lq;
                bf[nt][0] = __float_as_uint(Bs[(kb + lr) * SA + n0]);
                bf[nt][1] = __float_as_uint(Bs[(kb + lr + 4) * SA + n0]);
            }
#pragma unroll
            for (int mt = 0; mt < 4; mt++)
#pragma unroll
                for (int nt = 0; nt < 4; nt++)
                    mma_tf32(acc[mt][nt], a[mt], bf[nt]);
        }
        __syncthreads();
    }

    // epilogue
#pragma unroll
    for (int mt = 0; mt < 4; mt++) {
        const int row0 = rowBase + wm + mt * 16 + lq;
#pragma unroll
        for (int nt = 0; nt < 4; nt++) {
            const int col = colBase + wn + nt * 8 + lr * 2;
            float bx = 0.f, by = 0.f;
            if (epi >= 1) {
                float2 bb = *(const float2*)&bias[col];
                bx = bb.x; by = bb.y;
            }
            float v0 = acc[mt][nt][0] + bx;
            float v1 = acc[mt][nt][1] + by;
            float v2 = acc[mt][nt][2] + bx;
            float v3 = acc[mt][nt][3] + by;
            if (epi == 2) {
                v0 = gelu_exact(v0); v1 = gelu_exact(v1);
                v2 = gelu_exact(v2); v3 = gelu_exact(v3);
            }
            float2 w0 = make_float2(v0, v1);
            float2 w1 = make_float2(v2, v3);
            *(float2*)&C[(size_t)row0 * N + col]       = w0;
            *(float2*)&C[(size_t)(row0 + 8) * N + col] = w1;
        }
    }
}

// ---------------- token-type select + RoPE for Q (32 heads) ----------------
__global__ void __launch_bounds__(256)
select_rope_q(const int* __restrict__ ttm, const int* __restrict__ pos_ids)
{
    int idx = blockIdx.x * 256 + threadIdx.x;      // B*S*H*64
    int d  = idx & 63;
    int h  = (idx >> 6) & 31;
    int s  = (idx >> 11) & 1023;
    int b  = idx >> 21;
    int bs = b * S_ + s;

    bool is_e = (ttm[bs] == 1);
    const float* src = is_e ? &g_qe[((size_t)bs * 8 + (h & 7)) * 128]
                            : &g_qt[((size_t)bs * 32 + h) * 128];
    float x1 = src[d], x2 = src[d + 64];

    float inv = powf(10000.0f, -(float)d * (1.0f / 64.0f));
    float th  = (float)pos_ids[bs] * inv;
    float cs, sn; sincosf(th, &sn, &cs);

    float* dst = &g_q[(((size_t)b * 32 + h) * 1024 + s) * 128];
    dst[d]      = x1 * cs - x2 * sn;
    dst[d + 64] = x2 * cs + x1 * sn;
}

// ---------------- token-type select + RoPE for K, plain select for V (8 heads) ----------------
__global__ void __launch_bounds__(256)
select_rope_kv(const int* __restrict__ ttm, const int* __restrict__ pos_ids)
{
    int idx = blockIdx.x * 256 + threadIdx.x;      // B*S*8*64
    int d  = idx & 63;
    int h  = (idx >> 6) & 7;
    int s  = (idx >> 9) & 1023;
    int b  = idx >> 19;
    int bs = b * S_ + s;

    bool is_e = (ttm[bs] == 1);
    size_t srcOff = ((size_t)bs * 8 + h) * 128;
    const float* ks = is_e ? &g_ke[srcOff] : &g_kt[srcOff];
    const float* vs = is_e ? &g_ve[srcOff] : &g_vt[srcOff];

    float inv = powf(10000.0f, -(float)d * (1.0f / 64.0f));
    float th  = (float)pos_ids[bs] * inv;
    float cs, sn; sincosf(th, &sn, &cs);

    size_t dstOff = (((size_t)b * 8 + h) * 1024 + s) * 128;
    float k1 = ks[d], k2 = ks[d + 64];
    g_k[dstOff + d]      = k1 * cs - k2 * sn;
    g_k[dstOff + d + 64] = k2 * cs + k1 * sn;
    g_v[dstOff + d]      = vs[d];
    g_v[dstOff + d + 64] = vs[d + 64];
}

// ---------------- causal flash attention (GQA 32q -> 8kv), fp32, spill-free ----------------
// grid: (S/64, H, B), 256 threads. Dynamic smem: K,V tiles 64x128 (64KB).
// Q held in registers; scores processed 16 columns at a time, fully unrolled.
__global__ void __launch_bounds__(256)
flash_kernel()
{
    extern __shared__ float sm[];
    float* Ks = sm;
    float* Vs = sm + 64 * 128;

    const int qt  = blockIdx.x;
    const int h   = blockIdx.y;
    const int b   = blockIdx.z;
    const int tid = threadIdx.x;
    const int r   = tid >> 2;     // q-row within tile
    const int seg = tid & 3;      // 32-wide d slice

    const float SCALE = 0.08838834764831845f;  // 1/sqrt(128)

    const float* Qg = g_q + (((size_t)b * 32 + h) * 1024 + qt * 64 + r) * 128 + seg * 32;
    const float* Kg = g_k + ((size_t)b * 8 + (h & 7)) * 1024 * 128;
    const float* Vg = g_v + ((size_t)b * 8 + (h & 7)) * 1024 * 128;

    float4 Qr[8];
#pragma unroll
    for (int i = 0; i < 8; i++) Qr[i] = ((const float4*)Qg)[i];

    float m = -1e30f, l = 0.f;
    float4 Oa[8];
#pragma unroll
    for (int i = 0; i < 8; i++) Oa[i] = make_float4(0.f, 0.f, 0.f, 0.f);

    const int qrow = qt * 64 + r;

    for (int kt = 0; kt <= qt; kt++) {
        __syncthreads();
        for (int i = tid; i < 64 * 128 / 4; i += 256) {
            ((float4*)Ks)[i] = ((const float4*)(Kg + (size_t)kt * 64 * 128))[i];
            ((float4*)Vs)[i] = ((const float4*)(Vg + (size_t)kt * 64 * 128))[i];
        }
        __syncthreads();

        const bool diag = (kt == qt);

        for (int ch = 0; ch < 4; ch++) {
            float s[16];
#pragma unroll
            for (int j = 0; j < 16; j++) {
                const float4* Kc = (const float4*)(Ks + (ch * 16 + j) * 128 + seg * 32);
                float d = 0.f;
#pragma unroll
                for (int i = 0; i < 8; i++) {
                    float4 kk = Kc[i];
                    d += Qr[i].x * kk.x + Qr[i].y * kk.y
                       + Qr[i].z * kk.z + Qr[i].w * kk.w;
                }
                d += __shfl_xor_sync(0xffffffffu, d, 1);
                d += __shfl_xor_sync(0xffffffffu, d, 2);
                d *= SCALE;
                if (diag && (kt * 64 + ch * 16 + j > qrow)) d = -1e30f;
                s[j] = d;
            }

            float mloc = s[0];
#pragma unroll
            for (int j = 1; j < 16; j++) mloc = fmaxf(mloc, s[j]);
            float mnew = fmaxf(m, mloc);
            float corr = __expf(m - mnew);
            float sum = 0.f;
#pragma unroll
            for (int j = 0; j < 16; j++) {
                s[j] = __expf(s[j] - mnew);
                sum += s[j];
            }
            l = l * corr + sum;
            m = mnew;
#pragma unroll
            for (int i = 0; i < 8; i++) {
                Oa[i].x *= corr; Oa[i].y *= corr; Oa[i].z *= corr; Oa[i].w *= corr;
            }
#pragma unroll
            for (int j = 0; j < 16; j++) {
                float e = s[j];
                const float4* Vc = (const float4*)(Vs + (ch * 16 + j) * 128 + seg * 32);
#pragma unroll
                for (int i = 0; i < 8; i++) {
                    float4 vv = Vc[i];
                    Oa[i].x += e * vv.x; Oa[i].y += e * vv.y;
                    Oa[i].z += e * vv.z; Oa[i].w += e * vv.w;
                }
            }
        }
    }

    float invl = 1.0f / l;
    float4* Og = (float4*)(g_att + (((size_t)b * 1024 + qrow) * 32 + h) * 128 + seg * 32);
#pragma unroll
    for (int i = 0; i < 8; i++) {
        float4 o = Oa[i];
        o.x *= invl; o.y *= invl; o.z *= invl; o.w *= invl;
        Og[i] = o;
    }
}

// ---------------- mean over the 4 rep-groups: [B,S,32,128] -> [B,S,8,128] ----------------
__global__ void __launch_bounds__(256)
mean_heads()
{
    int idx = blockIdx.x * 256 + threadIdx.x;   // NTOK*1024
    int bs = idx >> 10;
    int w  = idx & 1023;
    int i  = w >> 7, d = w & 127;
    const float* base = g_att + (size_t)bs * 4096 + i * 128 + d;
    g_pre[idx] = 0.25f * (base[0] + base[8 * 128] + base[16 * 128] + base[24 * 128]);
}

// ---------------- final masking of the two output regions ----------------
__global__ void __launch_bounds__(256)
mask_outputs(float* __restrict__ out, const int* __restrict__ ttm)
{
    int idx = blockIdx.x * 256 + threadIdx.x;
    const int text_total = NTOK * HID_;
    if (idx < text_total) {
        int row = idx >> 12;                 // / 4096
        if (ttm[row] == 1) out[idx] = 0.f;
    } else {
        int j = idx - text_total;            // < NTOK*EHID_
        int row = j >> 10;                   // / 1024
        if (ttm[row] == 0) out[idx] = 0.f;
    }
}

// ---------------- host-side ----------------
static float* sym_addr(const void* sym) {
    void* p = nullptr;
    cudaGetSymbolAddress(&p, sym);
    return (float*)p;
}

extern "C" void kernel_launch(void* const* d_in, const int* in_sizes, int n_in,
                              void* d_out, int out_size)
{
    const float* x_text  = (const float*)d_in[0];
    const float* x_ent   = (const float*)d_in[1];
    const float* wq_t    = (const float*)d_in[2];
    const float* wk_t    = (const float*)d_in[3];
    const float* wv_t    = (const float*)d_in[4];
    const float* wo_t    = (const float*)d_in[5];
    const float* wq_e    = (const float*)d_in[6];
    const float* wk_e    = (const float*)d_in[7];
    const float* wv_e    = (const float*)d_in[8];
    const float* wo_e    = (const float*)d_in[9];
    const float* aq1_w   = (const float*)d_in[10];
    const float* aq1_b   = (const float*)d_in[11];
    const float* aq2_w   = (const float*)d_in[12];
    const float* aq2_b   = (const float*)d_in[13];
    const float* ak1_w   = (const float*)d_in[14];
    const float* ak1_b   = (const float*)d_in[15];
    const float* ak2_w   = (const float*)d_in[16];
    const float* ak2_b   = (const float*)d_in[17];
    const float* av1_w   = (const float*)d_in[18];
    const float* av1_b   = (const float*)d_in[19];
    const float* av2_w   = (const float*)d_in[20];
    const float* av2_b   = (const float*)d_in[21];
    const float* ao1_w   = (const float*)d_in[22];
    const float* ao1_b   = (const float*)d_in[23];
    const float* ao2_w   = (const float*)d_in[24];
    const float* ao2_b   = (const float*)d_in[25];
    // d_in[26] = attention_mask (pure causal; implemented analytically)
    const int*   ttm     = (const int*)d_in[27];
    const int*   pos_ids = (const int*)d_in[28];

    float* out = (float*)d_out;
    float* out_text = out;                         // [2048, 4096]
    float* out_ent  = out + (size_t)NTOK * HID_;   // [2048, 1024]

    float* p_qt  = sym_addr(g_qt);
    float* p_kt  = sym_addr(g_kt);
    float* p_vt  = sym_addr(g_vt);
    float* p_pre = sym_addr(g_pre);
    float* p_tmp = sym_addr(g_tmp);
    float* p_qe  = sym_addr(g_qe);
    float* p_ke  = sym_addr(g_ke);
    float* p_ve  = sym_addr(g_ve);
    float* p_att = sym_addr(g_att);
    float* p_oe  = sym_addr(g_oe);

    static bool attr_set = false;
    if (!attr_set) {
        cudaFuncSetAttribute(flash_kernel,
                             cudaFuncAttributeMaxDynamicSharedMemorySize, 65536);
        attr_set = true;
    }

    dim3 blk(256);
    auto gemm = [&](const float* A, const float* Bm, const float* bias,
                    float* C, int M, int N, int K, int epi) {
        dim3 grid(N / 128, M / 128);
        gemm_tc<<<grid, blk>>>(A, Bm, bias, C, M, N, K, epi);
    };

    // ---- text projections ----
    gemm(x_text, wq_t, nullptr, p_qt, NTOK, HID_, HID_, 0);
    gemm(x_text, wk_t, nullptr, p_kt, NTOK, EHID_, HID_, 0);
    gemm(x_text, wv_t, nullptr, p_vt, NTOK, EHID_, HID_, 0);

    // ---- entity projections + adapters ----
    gemm(x_ent, wq_e, nullptr, p_pre, NTOK, EHID_, EHID_, 0);
    gemm(p_pre, aq1_w, aq1_b, p_tmp, NHV, AH_, D_, 2);
    gemm(p_tmp, aq2_w, aq2_b, p_qe, NHV, D_, AH_, 1);

    gemm(x_ent, wk_e, nullptr, p_pre, NTOK, EHID_, EHID_, 0);
    gemm(p_pre, ak1_w, ak1_b, p_tmp, NHV, AH_, D_, 2);
    gemm(p_tmp, ak2_w, ak2_b, p_ke, NHV, D_, AH_, 1);

    gemm(x_ent, wv_e, nullptr, p_pre, NTOK, EHID_, EHID_, 0);
    gemm(p_pre, av1_w, av1_b, p_tmp, NHV, AH_, D_, 2);
    gemm(p_tmp, av2_w, av2_b, p_ve, NHV, D_, AH_, 1);

    // ---- select by token type + RoPE ----
    select_rope_q <<<(B_*S_*H_*64) / 256, blk>>>(ttm, pos_ids);
    select_rope_kv<<<(B_*S_*KVH_*64) / 256, blk>>>(ttm, pos_ids);

    // ---- causal flash attention (GQA 32->8) ----
    {
        dim3 grid(S_ / 64, H_, B_);
        flash_kernel<<<grid, blk, 65536>>>();
    }

    // ---- text output projection (into d_out) ----
    gemm(p_att, wo_t, nullptr, out_text, NTOK, HID_, HID_, 0);

    // ---- entity output path: mean -> adapter -> projection ----
    mean_heads<<<(NTOK * EHID_) / 256, blk>>>();
    gemm(p_pre, ao1_w, ao1_b, p_tmp, NHV, AH_, D_, 2);
    gemm(p_tmp, ao2_w, ao2_b, p_oe, NHV, D_, AH_, 1);
    gemm(p_oe, wo_e, nullptr, out_ent, NTOK, EHID_, EHID_, 0);

    // ---- token-type masking of both regions ----
    {
        int total = NTOK * HID_ + NTOK * EHID_;
        mask_outputs<<<(total + 255) / 256, blk>>>(out, ttm);
    }
}

// round 5
// speedup vs baseline: 2.1375x; 1.1595x over previous
#include <cuda_runtime.h>
#include <math.h>
#include <stdint.h>

// ---------------- problem constants ----------------
#define B_    2
#define S_    1024
#define HID_  4096
#define H_    32
#define D_    128
#define KVH_  8
#define EHID_ 1024
#define EH_   8
#define AH_   256
#define NTOK  (B_*S_)          // 2048
#define NHV   (NTOK*EH_)       // 16384 per-head vectors for adapters

// ---------------- scratch (static device memory; no allocation) ----------------
__device__ float g_qt [NTOK*HID_];    // text Q       [B,S,32,128]
__device__ float g_kt [NTOK*EHID_];   // text K base  [B,S,8,128]
__device__ float g_vt [NTOK*EHID_];   // text V base  [B,S,8,128]
__device__ float g_pre[NTOK*EHID_];   // entity pre-adapter / mean buffer
__device__ float g_tmp[NHV*AH_];      // adapter hidden [16384,256]
__device__ float g_qe [NTOK*EHID_];   // entity Q base [B,S,8,128]
__device__ float g_ke [NTOK*EHID_];
__device__ float g_ve [NTOK*EHID_];
__device__ float g_q  [NTOK*HID_];    // roped Q [B,H,S,D]
__device__ float g_k  [NTOK*EHID_];   // roped K [B,8,S,D]
__device__ float g_v  [NTOK*EHID_];   // V       [B,8,S,D]
__device__ float g_att[NTOK*HID_];    // attention out [B,S,H,D] (tf32-rounded)
__device__ float g_oe [NTOK*EHID_];   // ao-adapter out

// rounded (tf32) copies of GEMM inputs (so cp.async path needs no cvt)
__device__ float r_xt [NTOK*HID_];
__device__ float r_xe [NTOK*EHID_];
__device__ float r_wqt[HID_*HID_];
__device__ float r_wkt[HID_*KVH_*D_];
__device__ float r_wvt[HID_*KVH_*D_];
__device__ float r_wot[HID_*HID_];
__device__ float r_wqe[EHID_*EHID_];
__device__ float r_wke[EHID_*EHID_];
__device__ float r_wve[EHID_*EHID_];
__device__ float r_woe[EHID_*EHID_];
__device__ float r_aq1[D_*AH_], r_aq2[AH_*D_];
__device__ float r_ak1[D_*AH_], r_ak2[AH_*D_];
__device__ float r_av1[D_*AH_], r_av2[AH_*D_];
__device__ float r_ao1[D_*AH_], r_ao2[AH_*D_];

// ---------------- helpers ----------------
__device__ __forceinline__ float gelu_exact(float x) {
    return 0.5f * x * (1.0f + erff(x * 0.70710678118654752f));
}

__device__ __forceinline__ uint32_t f2tf32(float x) {
    uint32_t r;
    asm("cvt.rna.tf32.f32 %0, %1;" : "=r"(r) : "f"(x));
    return r;
}
__device__ __forceinline__ float tf32r(float x) {
    return __uint_as_float(f2tf32(x));
}

__device__ __forceinline__ void mma_tf32(float c[4], const uint32_t a[4], const uint32_t b[2]) {
    asm volatile(
        "mma.sync.aligned.m16n8k8.row.col.f32.tf32.tf32.f32 "
        "{%0,%1,%2,%3}, {%4,%5,%6,%7}, {%8,%9}, {%0,%1,%2,%3};"
        : "+f"(c[0]), "+f"(c[1]), "+f"(c[2]), "+f"(c[3])
        : "r"(a[0]), "r"(a[1]), "r"(a[2]), "r"(a[3]), "r"(b[0]), "r"(b[1]));
}

__device__ __forceinline__ void cp_async16(void* smem_dst, const void* gsrc) {
    uint32_t s = (uint32_t)__cvta_generic_to_shared(smem_dst);
    asm volatile("cp.async.cg.shared.global [%0], [%1], 16;\n" :: "r"(s), "l"(gsrc));
}
#define CP_COMMIT() asm volatile("cp.async.commit_group;\n" ::)
#define CP_WAIT1()  asm volatile("cp.async.wait_group 1;\n" ::)

// ---------------- tf32 rounding pre-pass (float4) ----------------
__global__ void __launch_bounds__(256)
round4_k(const float* __restrict__ in, float* __restrict__ out, int n4)
{
    int i = blockIdx.x * 256 + threadIdx.x;
    if (i >= n4) return;
    float4 v = ((const float4*)in)[i];
    v.x = tf32r(v.x); v.y = tf32r(v.y); v.z = tf32r(v.z); v.w = tf32r(v.w);
    ((float4*)out)[i] = v;
}

// ---------------- TF32 tensor-core GEMM, cp.async double-buffered ----------------
// C[M,N] = A[M,K] @ B[K,N]. Inputs must already be tf32-rounded fp32.
// CTA tile 128x128, BK=32, 256 threads = 8 warps (2M x 4N), warp tile 64x32.
// epi bits: 1=+bias, 2=gelu, 4=round output to tf32.
#define ASTR 36
#define BSTR 136
#define A_TF (128*ASTR)            // 4608 floats
#define B_TF (32*BSTR)             // 4352 floats
#define STG  (A_TF + B_TF)         // 8960 floats per stage
#define GEMM_SMEM (2*STG*4)        // 71680 bytes

__global__ void __launch_bounds__(256, 2)
gemm_tc(const float* __restrict__ A, const float* __restrict__ Bm,
        const float* __restrict__ bias, float* __restrict__ C,
        int M, int N, int K, int epi)
{
    extern __shared__ float sm[];
    float* Abuf[2] = { sm,        sm + STG };
    float* Bbuf[2] = { sm + A_TF, sm + STG + A_TF };

    const int tid  = threadIdx.x;
    const int lane = tid & 31;
    const int lq   = lane >> 2;     // 0..7
    const int lr   = lane & 3;      // 0..3
    const int warp = tid >> 5;
    const int wm   = (warp & 1) * 64;
    const int wn   = (warp >> 1) * 32;
    const int rowBase = blockIdx.y * 128;
    const int colBase = blockIdx.x * 128;

    const float* Ag = A  + (size_t)rowBase * K;
    const float* Bg = Bm + colBase;

    // per-thread copy coordinates
    const int a_r = tid >> 1;                 // with i-loop: id = tid + i*256
    (void)a_r;

    float acc[4][4][4];
#pragma unroll
    for (int mt = 0; mt < 4; mt++)
#pragma unroll
        for (int nt = 0; nt < 4; nt++)
#pragma unroll
            for (int i = 0; i < 4; i++) acc[mt][nt][i] = 0.f;

    const int KT = K >> 5;

    // --- copy issue helper (A: 1024 16B chunks, B: 1024 16B chunks) ---
    auto issue_copy = [&](int stage, int k0) {
        float* As = Abuf[stage];
        float* Bs = Bbuf[stage];
#pragma unroll
        for (int i = 0; i < 4; i++) {
            int id = tid + i * 256;
            int r = id >> 3, g = id & 7;           // A tile 128 rows x 8 chunks
            cp_async16(&As[r * ASTR + g * 4], Ag + (size_t)r * K + k0 + g * 4);
        }
#pragma unroll
        for (int i = 0; i < 4; i++) {
            int id = tid + i * 256;
            int r = id >> 5, g = id & 31;          // B tile 32 rows x 32 chunks
            cp_async16(&Bs[r * BSTR + g * 4], Bg + (size_t)(k0 + r) * N + g * 4);
        }
    };

    issue_copy(0, 0);
    CP_COMMIT();
    if (KT > 1) issue_copy(1, 32);
    CP_COMMIT();
    CP_WAIT1();          // stage 0 ready
    __syncthreads();

    for (int kt = 0; kt < KT; kt++) {
        const int cur = kt & 1;
        const float* As = Abuf[cur];
        const float* Bs = Bbuf[cur];

#pragma unroll
        for (int ks = 0; ks < 4; ks++) {
            const int kb = ks * 8;
            uint32_t a[4][4], bf[4][2];
#pragma unroll
            for (int mt = 0; mt < 4; mt++) {
                int m0 = wm + mt * 16 + lq;
                a[mt][0] = __float_as_uint(As[(m0)     * ASTR + kb + lr]);
                a[mt][1] = __float_as_uint(As[(m0 + 8) * ASTR + kb + lr]);
                a[mt][2] = __float_as_uint(As[(m0)     * ASTR + kb + lr + 4]);
                a[mt][3] = __float_as_uint(As[(m0 + 8) * ASTR + kb + lr + 4]);
            }
#pragma unroll
            for (int nt = 0; nt < 4; nt++) {
                int n0 = wn + nt * 8 + lq;
                bf[nt][0] = __float_as_uint(Bs[(kb + lr)     * BSTR + n0]);
                bf[nt][1] = __float_as_uint(Bs[(kb + lr + 4) * BSTR + n0]);
            }
#pragma unroll
            for (int mt = 0; mt < 4; mt++)
#pragma unroll
                for (int nt = 0; nt < 4; nt++)
                    mma_tf32(acc[mt][nt], a[mt], bf[nt]);
        }

        __syncthreads();                 // everyone done reading 'cur'
        if (kt + 2 < KT) issue_copy(cur, (kt + 2) * 32);
        CP_COMMIT();                     // always commit (possibly empty group)
        CP_WAIT1();                      // next stage ready
        __syncthreads();
    }

    // epilogue
#pragma unroll
    for (int mt = 0; mt < 4; mt++) {
        const int row0 = rowBase + wm + mt * 16 + lq;
#pragma unroll
        for (int nt = 0; nt < 4; nt++) {
            const int col = colBase + wn + nt * 8 + lr * 2;
            float bx = 0.f, by = 0.f;
            if (epi & 1) {
                float2 bb = *(const float2*)&bias[col];
                bx = bb.x; by = bb.y;
            }
            float v0 = acc[mt][nt][0] + bx;
            float v1 = acc[mt][nt][1] + by;
            float v2 = acc[mt][nt][2] + bx;
            float v3 = acc[mt][nt][3] + by;
            if (epi & 2) {
                v0 = gelu_exact(v0); v1 = gelu_exact(v1);
                v2 = gelu_exact(v2); v3 = gelu_exact(v3);
            }
            if (epi & 4) {
                v0 = tf32r(v0); v1 = tf32r(v1); v2 = tf32r(v2); v3 = tf32r(v3);
            }
            *(float2*)&C[(size_t)row0 * N + col]       = make_float2(v0, v1);
            *(float2*)&C[(size_t)(row0 + 8) * N + col] = make_float2(v2, v3);
        }
    }
}

// ---------------- token-type select + RoPE for Q (32 heads) ----------------
__global__ void __launch_bounds__(256)
select_rope_q(const int* __restrict__ ttm, const int* __restrict__ pos_ids)
{
    int idx = blockIdx.x * 256 + threadIdx.x;      // B*S*H*64
    int d  = idx & 63;
    int h  = (idx >> 6) & 31;
    int s  = (idx >> 11) & 1023;
    int b  = idx >> 21;
    int bs = b * S_ + s;

    bool is_e = (ttm[bs] == 1);
    const float* src = is_e ? &g_qe[((size_t)bs * 8 + (h & 7)) * 128]
                            : &g_qt[((size_t)bs * 32 + h) * 128];
    float x1 = src[d], x2 = src[d + 64];

    float inv = powf(10000.0f, -(float)d * (1.0f / 64.0f));
    float th  = (float)pos_ids[bs] * inv;
    float cs, sn; sincosf(th, &sn, &cs);

    float* dst = &g_q[(((size_t)b * 32 + h) * 1024 + s) * 128];
    dst[d]      = x1 * cs - x2 * sn;
    dst[d + 64] = x2 * cs + x1 * sn;
}

// ---------------- token-type select + RoPE for K, plain select for V (8 heads) ----------------
__global__ void __launch_bounds__(256)
select_rope_kv(const int* __restrict__ ttm, const int* __restrict__ pos_ids)
{
    int idx = blockIdx.x * 256 + threadIdx.x;      // B*S*8*64
    int d  = idx & 63;
    int h  = (idx >> 6) & 7;
    int s  = (idx >> 9) & 1023;
    int b  = idx >> 19;
    int bs = b * S_ + s;

    bool is_e = (ttm[bs] == 1);
    size_t srcOff = ((size_t)bs * 8 + h) * 128;
    const float* ks = is_e ? &g_ke[srcOff] : &g_kt[srcOff];
    const float* vs = is_e ? &g_ve[srcOff] : &g_vt[srcOff];

    float inv = powf(10000.0f, -(float)d * (1.0f / 64.0f));
    float th  = (float)pos_ids[bs] * inv;
    float cs, sn; sincosf(th, &sn, &cs);

    size_t dstOff = (((size_t)b * 8 + h) * 1024 + s) * 128;
    float k1 = ks[d], k2 = ks[d + 64];
    g_k[dstOff + d]      = k1 * cs - k2 * sn;
    g_k[dstOff + d + 64] = k2 * cs + k1 * sn;
    g_v[dstOff + d]      = vs[d];
    g_v[dstOff + d + 64] = vs[d + 64];
}

// ---------------- causal flash attention (GQA 32q -> 8kv), fp32 ----------------
// grid: (S/64, H, B), 256 threads. Dynamic smem: K,V tiles 64x128 (64KB).
__global__ void __launch_bounds__(256)
flash_kernel()
{
    extern __shared__ float smf[];
    float* Ks = smf;
    float* Vs = smf + 64 * 128;

    const int qt  = blockIdx.x;
    const int h   = blockIdx.y;
    const int b   = blockIdx.z;
    const int tid = threadIdx.x;
    const int r   = tid >> 2;     // q-row within tile
    const int seg = tid & 3;      // 32-wide d slice

    const float SCALE = 0.08838834764831845f;  // 1/sqrt(128)

    const float* Qg = g_q + (((size_t)b * 32 + h) * 1024 + qt * 64 + r) * 128 + seg * 32;
    const float* Kg = g_k + ((size_t)b * 8 + (h & 7)) * 1024 * 128;
    const float* Vg = g_v + ((size_t)b * 8 + (h & 7)) * 1024 * 128;

    float4 Qr[8];
#pragma unroll
    for (int i = 0; i < 8; i++) Qr[i] = ((const float4*)Qg)[i];

    float m = -1e30f, l = 0.f;
    float4 Oa[8];
#pragma unroll
    for (int i = 0; i < 8; i++) Oa[i] = make_float4(0.f, 0.f, 0.f, 0.f);

    const int qrow = qt * 64 + r;

    for (int kt = 0; kt <= qt; kt++) {
        __syncthreads();
        for (int i = tid; i < 64 * 128 / 4; i += 256) {
            ((float4*)Ks)[i] = ((const float4*)(Kg + (size_t)kt * 64 * 128))[i];
            ((float4*)Vs)[i] = ((const float4*)(Vg + (size_t)kt * 64 * 128))[i];
        }
        __syncthreads();

        const bool diag = (kt == qt);

        for (int ch = 0; ch < 4; ch++) {
            float s[16];
#pragma unroll
            for (int j = 0; j < 16; j++) {
                const float4* Kc = (const float4*)(Ks + (ch * 16 + j) * 128 + seg * 32);
                float d = 0.f;
#pragma unroll
                for (int i = 0; i < 8; i++) {
                    float4 kk = Kc[i];
                    d += Qr[i].x * kk.x + Qr[i].y * kk.y
                       + Qr[i].z * kk.z + Qr[i].w * kk.w;
                }
                d += __shfl_xor_sync(0xffffffffu, d, 1);
                d += __shfl_xor_sync(0xffffffffu, d, 2);
                d *= SCALE;
                if (diag && (kt * 64 + ch * 16 + j > qrow)) d = -1e30f;
                s[j] = d;
            }

            float mloc = s[0];
#pragma unroll
            for (int j = 1; j < 16; j++) mloc = fmaxf(mloc, s[j]);
            float mnew = fmaxf(m, mloc);
            float corr = __expf(m - mnew);
            float sum = 0.f;
#pragma unroll
            for (int j = 0; j < 16; j++) {
                s[j] = __expf(s[j] - mnew);
                sum += s[j];
            }
            l = l * corr + sum;
            m = mnew;
#pragma unroll
            for (int i = 0; i < 8; i++) {
                Oa[i].x *= corr; Oa[i].y *= corr; Oa[i].z *= corr; Oa[i].w *= corr;
            }
#pragma unroll
            for (int j = 0; j < 16; j++) {
                float e = s[j];
                const float4* Vc = (const float4*)(Vs + (ch * 16 + j) * 128 + seg * 32);
#pragma unroll
                for (int i = 0; i < 8; i++) {
                    float4 vv = Vc[i];
                    Oa[i].x += e * vv.x; Oa[i].y += e * vv.y;
                    Oa[i].z += e * vv.z; Oa[i].w += e * vv.w;
                }
            }
        }
    }

    float invl = 1.0f / l;
    // rounded to tf32: g_att feeds downstream GEMMs directly via cp.async
    float4* Og = (float4*)(g_att + (((size_t)b * 1024 + qrow) * 32 + h) * 128 + seg * 32);
#pragma unroll
    for (int i = 0; i < 8; i++) {
        float4 o = Oa[i];
        o.x = tf32r(o.x * invl); o.y = tf32r(o.y * invl);
        o.z = tf32r(o.z * invl); o.w = tf32r(o.w * invl);
        Og[i] = o;
    }
}

// ---------------- mean over the 4 rep-groups: [B,S,32,128] -> [B,S,8,128] ----------------
__global__ void __launch_bounds__(256)
mean_heads()
{
    int idx = blockIdx.x * 256 + threadIdx.x;   // NTOK*1024
    int bs = idx >> 10;
    int w  = idx & 1023;
    int i  = w >> 7, d = w & 127;
    const float* base = g_att + (size_t)bs * 4096 + i * 128 + d;
    g_pre[idx] = tf32r(0.25f * (base[0] + base[8 * 128] + base[16 * 128] + base[24 * 128]));
}

// ---------------- final masking of the two output regions ----------------
__global__ void __launch_bounds__(256)
mask_outputs(float* __restrict__ out, const int* __restrict__ ttm)
{
    int idx = blockIdx.x * 256 + threadIdx.x;
    const int text_total = NTOK * HID_;
    if (idx < text_total) {
        int row = idx >> 12;                 // / 4096
        if (ttm[row] == 1) out[idx] = 0.f;
    } else {
        int j = idx - text_total;            // < NTOK*EHID_
        int row = j >> 10;                   // / 1024
        if (ttm[row] == 0) out[idx] = 0.f;
    }
}

// ---------------- host-side ----------------
static float* sym_addr(const void* sym) {
    void* p = nullptr;
    cudaGetSymbolAddress(&p, sym);
    return (float*)p;
}

extern "C" void kernel_launch(void* const* d_in, const int* in_sizes, int n_in,
                              void* d_out, int out_size)
{
    const float* x_text  = (const float*)d_in[0];
    const float* x_ent   = (const float*)d_in[1];
    const float* wq_t    = (const float*)d_in[2];
    const float* wk_t    = (const float*)d_in[3];
    const float* wv_t    = (const float*)d_in[4];
    const float* wo_t    = (const float*)d_in[5];
    const float* wq_e    = (const float*)d_in[6];
    const float* wk_e    = (const float*)d_in[7];
    const float* wv_e    = (const float*)d_in[8];
    const float* wo_e    = (const float*)d_in[9];
    const float* aq1_w   = (const float*)d_in[10];
    const float* aq1_b   = (const float*)d_in[11];
    const float* aq2_w   = (const float*)d_in[12];
    const float* aq2_b   = (const float*)d_in[13];
    const float* ak1_w   = (const float*)d_in[14];
    const float* ak1_b   = (const float*)d_in[15];
    const float* ak2_w   = (const float*)d_in[16];
    const float* ak2_b   = (const float*)d_in[17];
    const float* av1_w   = (const float*)d_in[18];
    const float* av1_b   = (const float*)d_in[19];
    const float* av2_w   = (const float*)d_in[20];
    const float* av2_b   = (const float*)d_in[21];
    const float* ao1_w   = (const float*)d_in[22];
    const float* ao1_b   = (const float*)d_in[23];
    const float* ao2_w   = (const float*)d_in[24];
    const float* ao2_b   = (const float*)d_in[25];
    // d_in[26] = attention_mask (pure causal; implemented analytically)
    const int*   ttm     = (const int*)d_in[27];
    const int*   pos_ids = (const int*)d_in[28];

    float* out = (float*)d_out;
    float* out_text = out;                         // [2048, 4096]
    float* out_ent  = out + (size_t)NTOK * HID_;   // [2048, 1024]

    float* p_pre = sym_addr(g_pre);
    float* p_tmp = sym_addr(g_tmp);
    float* p_qt  = sym_addr(g_qt);
    float* p_kt  = sym_addr(g_kt);
    float* p_vt  = sym_addr(g_vt);
    float* p_qe  = sym_addr(g_qe);
    float* p_ke  = sym_addr(g_ke);
    float* p_ve  = sym_addr(g_ve);
    float* p_att = sym_addr(g_att);
    float* p_oe  = sym_addr(g_oe);

    float* p_rxt  = sym_addr(r_xt);
    float* p_rxe  = sym_addr(r_xe);
    float* p_rwqt = sym_addr(r_wqt);
    float* p_rwkt = sym_addr(r_wkt);
    float* p_rwvt = sym_addr(r_wvt);
    float* p_rwot = sym_addr(r_wot);
    float* p_rwqe = sym_addr(r_wqe);
    float* p_rwke = sym_addr(r_wke);
    float* p_rwve = sym_addr(r_wve);
    float* p_rwoe = sym_addr(r_woe);
    float* p_raq1 = sym_addr(r_aq1);
    float* p_raq2 = sym_addr(r_aq2);
    float* p_rak1 = sym_addr(r_ak1);
    float* p_rak2 = sym_addr(r_ak2);
    float* p_rav1 = sym_addr(r_av1);
    float* p_rav2 = sym_addr(r_av2);
    float* p_rao1 = sym_addr(r_ao1);
    float* p_rao2 = sym_addr(r_ao2);

    cudaFuncSetAttribute(flash_kernel,
                         cudaFuncAttributeMaxDynamicSharedMemorySize, 65536);
    cudaFuncSetAttribute(gemm_tc,
                         cudaFuncAttributeMaxDynamicSharedMemorySize, GEMM_SMEM);

    dim3 blk(256);

    auto rnd = [&](const float* in, float* outp, int n) {
        int n4 = n / 4;
        round4_k<<<(n4 + 255) / 256, blk>>>(in, outp, n4);
    };

    // ---- pre-round all GEMM inputs to tf32 ----
    rnd(x_text, p_rxt, NTOK * HID_);
    rnd(x_ent,  p_rxe, NTOK * EHID_);
    rnd(wq_t, p_rwqt, HID_ * HID_);
    rnd(wk_t, p_rwkt, HID_ * KVH_ * D_);
    rnd(wv_t, p_rwvt, HID_ * KVH_ * D_);
    rnd(wo_t, p_rwot, HID_ * HID_);
    rnd(wq_e, p_rwqe, EHID_ * EHID_);
    rnd(wk_e, p_rwke, EHID_ * EHID_);
    rnd(wv_e, p_rwve, EHID_ * EHID_);
    rnd(wo_e, p_rwoe, EHID_ * EHID_);
    rnd(aq1_w, p_raq1, D_ * AH_);  rnd(aq2_w, p_raq2, AH_ * D_);
    rnd(ak1_w, p_rak1, D_ * AH_);  rnd(ak2_w, p_rak2, AH_ * D_);
    rnd(av1_w, p_rav1, D_ * AH_);  rnd(av2_w, p_rav2, AH_ * D_);
    rnd(ao1_w, p_rao1, D_ * AH_);  rnd(ao2_w, p_rao2, AH_ * D_);

    auto gemm = [&](const float* A, const float* Bm, const float* bias,
                    float* C, int M, int N, int K, int epi) {
        dim3 grid(N / 128, M / 128);
        gemm_tc<<<grid, blk, GEMM_SMEM>>>(A, Bm, bias, C, M, N, K, epi);
    };

    // ---- text projections (outputs feed rope only: no rounding) ----
    gemm(p_rxt, p_rwqt, nullptr, p_qt, NTOK, HID_, HID_, 0);
    gemm(p_rxt, p_rwkt, nullptr, p_kt, NTOK, EHID_, HID_, 0);
    gemm(p_rxt, p_rwvt, nullptr, p_vt, NTOK, EHID_, HID_, 0);

    // ---- entity projections + adapters ----
    // proj output feeds adapter GEMM -> round (epi|4). adapter1 output feeds
    // adapter2 -> bias+gelu+round (7). adapter2 output feeds rope -> bias only (1).
    gemm(p_rxe, p_rwqe, nullptr, p_pre, NTOK, EHID_, EHID_, 4);
    gemm(p_pre, p_raq1, aq1_b, p_tmp, NHV, AH_, D_, 7);
    gemm(p_tmp, p_raq2, aq2_b, p_qe, NHV, D_, AH_, 1);

    gemm(p_rxe, p_rwke, nullptr, p_pre, NTOK, EHID_, EHID_, 4);
    gemm(p_pre, p_rak1, ak1_b, p_tmp, NHV, AH_, D_, 7);
    gemm(p_tmp, p_rak2, ak2_b, p_ke, NHV, D_, AH_, 1);

    gemm(p_rxe, p_rwve, nullptr, p_pre, NTOK, EHID_, EHID_, 4);
    gemm(p_pre, p_rav1, av1_b, p_tmp, NHV, AH_, D_, 7);
    gemm(p_tmp, p_rav2, av2_b, p_ve, NHV, D_, AH_, 1);

    // ---- select by token type + RoPE ----
    select_rope_q <<<(B_*S_*H_*64) / 256, blk>>>(ttm, pos_ids);
    select_rope_kv<<<(B_*S_*KVH_*64) / 256, blk>>>(ttm, pos_ids);

    // ---- causal flash attention (GQA 32->8); writes tf32-rounded g_att ----
    {
        dim3 grid(S_ / 64, H_, B_);
        flash_kernel<<<grid, blk, 65536>>>();
    }

    // ---- text output projection (into d_out; final, no rounding) ----
    gemm(p_att, p_rwot, nullptr, out_text, NTOK, HID_, HID_, 0);

    // ---- entity output path: mean (rounds) -> adapter -> projection ----
    mean_heads<<<(NTOK * EHID_) / 256, blk>>>();
    gemm(p_pre, p_rao1, ao1_b, p_tmp, NHV, AH_, D_, 7);
    gemm(p_tmp, p_rao2, ao2_b, p_oe, NHV, D_, AH_, 5);   // bias + round (feeds wo_e GEMM)
    gemm(p_oe, p_rwoe, nullptr, out_ent, NTOK, EHID_, EHID_, 0);

    // ---- token-type masking of both regions ----
    {
        int total = NTOK * HID_ + NTOK * EHID_;
        mask_outputs<<<(total + 255) / 256, blk>>>(out, ttm);
    }
}